// round 15
// baseline (speedup 1.0000x reference)
#include <cuda_runtime.h>
#include <cuda_fp16.h>
#include <cstdint>
#include <cstddef>

// ---------------------------------------------------------------------------
// Problem constants
// ---------------------------------------------------------------------------
#define NB      98304
#define PERIOD  24
#define BB      (NB / PERIOD)     // 4096
#define WPAD    152               // padded K stride (halves) for LSTM weights

__constant__ int c_EI[44] = {0,0,0,0, 1,1,1, 2,2,2, 3,3, 4,4, 5,5,5, 6,6,6,6,
                             7,7,7, 8,8,8,8, 9,9,9,9, 10,10,10,10,10,10,10,
                             11,11,11,11,11};
__constant__ int c_EJ[44] = {0,5,10,11, 1,7,10, 2,6,11, 3,6, 4,5, 0,4,5,
                             2,3,6,10, 1,7,9, 8,9,10,11, 7,8,9,10,
                             0,1,6,8,9,10,11, 0,2,8,10,11};
__constant__ int c_RS[13] = {0,4,7,10,12,14,17,21,24,28,32,39,44};

// ---------------------------------------------------------------------------
// Scratch layout (float units)
// ---------------------------------------------------------------------------
#define OFF_X16   ((size_t)0)                        // fp16 [NB][288]
#define OFF_H2    (OFF_X16  + (size_t)NB * 144)      // fp16 [NB][144]
#define OFF_XPRE  (OFF_H2   + (size_t)NB * 72)       // fp16 [24][72][256][128] tiles
#define OFF_Y0    (OFF_XPRE + (size_t)NB * 288)      // fp16 [24][BB][144]
#define OFF_YD0   (OFF_Y0   + (size_t)NB * 72)
#define OFF_YD1   (OFF_YD0  + (size_t)NB * 72)
#define OFF_H4    (OFF_YD1  + (size_t)NB * 72)       // fp16 [NB][288]
#define OFF_ENC1  (OFF_H4   + (size_t)NB * 144)      // fp16 [BB][144]
#define OFF_PART  (OFF_ENC1 + (size_t)BB * 72)       // fp32 [5][NB]
#define OFF_PROBS (OFF_PART + (size_t)5 * NB)        // fp32 4*576
#define OFF_M     (OFF_PROBS + 2304)                 // fp16 M1..M4
#define SZ_M      ((192*288 + 192*192 + 192*144 + 320*192) / 2)
#define OFF_W16   (OFF_M + SZ_M)
#define OFF_BR    (OFF_W16 + (size_t)7 * 576 * WPAD / 2)
#define OFF_FW16  (OFF_BR + 4 * 576)
#define SCRATCH_TOTAL (OFF_FW16 + (size_t)320 * 288 / 2)

__device__ __align__(128) float g_scratch[SCRATCH_TOTAL];

__device__ __forceinline__ float tanha(float x) {
    float y;
    asm("tanh.approx.f32 %0, %1;" : "=f"(y) : "f"(x));
    return y;
}
__device__ __forceinline__ float sigm(float x) { return fmaf(tanha(0.5f * x), 0.5f, 0.5f); }
__device__ __forceinline__ float felu(float x) { return x > 0.f ? x : (__expf(x) - 1.f); }

__device__ __forceinline__ uint32_t smem_u32(const void* p) {
    return (uint32_t)__cvta_generic_to_shared(p);
}
__device__ __forceinline__ void ldm_x4(uint32_t& r0, uint32_t& r1, uint32_t& r2,
                                       uint32_t& r3, const void* p) {
    asm volatile("ldmatrix.sync.aligned.m8n8.x4.shared.b16 {%0,%1,%2,%3}, [%4];"
                 : "=r"(r0), "=r"(r1), "=r"(r2), "=r"(r3) : "r"(smem_u32(p)));
}
__device__ __forceinline__ void cp16(void* dst, const void* src) {
    asm volatile("cp.async.cg.shared.global [%0], [%1], 16;"
                 :: "r"(smem_u32(dst)), "l"(src));
}
__device__ __forceinline__ void cp_commit() {
    asm volatile("cp.async.commit_group;");
}
template <int N>
__device__ __forceinline__ void cp_wait() {
    asm volatile("cp.async.wait_group %0;" :: "n"(N));
}
#define MMA16(d0,d1,d2,d3,a0,a1,a2,a3,b0,b1)                                    \
    asm volatile("mma.sync.aligned.m16n8k16.row.col.f32.f16.f16.f32 "           \
                 "{%0,%1,%2,%3}, {%4,%5,%6,%7}, {%8,%9}, {%0,%1,%2,%3};"        \
                 : "+f"(d0), "+f"(d1), "+f"(d2), "+f"(d3)                       \
                 : "r"(a0), "r"(a1), "r"(a2), "r"(a3), "r"(b0), "r"(b1))

// ---------------------------------------------------------------------------
// Gate-pair column mapping
// ---------------------------------------------------------------------------
__device__ __forceinline__ void col_to_jg(int n, int& j, int& g) {
    int warp = n / 144, r = n - warp * 144;
    int half = r / 72, rr = r - half * 72;
    int u = rr >> 1, b = rr & 1;
    g = half * 2 + b;
    j = warp * 36 + u;
}

// ---------------------------------------------------------------------------
// Merged prep kernel (weights + biases + FC transpose + x conversion)
// ---------------------------------------------------------------------------
struct PrepArgs {
    const float* wsrc[7];
    const float* bih[4];
    const float* bhh[4];
    const float* fW;
    const float* x;
};
#define PREP_W  ((size_t)7 * 576 * WPAD)
#define PREP_B  (4 * 576)
#define PREP_F  (320 * 288)
#define PREP_X  ((size_t)NB * 288)
#define PREP_TOT (PREP_W + PREP_B + PREP_F + PREP_X)

__global__ void prep_all(PrepArgs args, __half* w16, float* br, __half* fw16,
                         __half* x16) {
    for (size_t idx = (size_t)blockIdx.x * 256 + threadIdx.x; idx < PREP_TOT;
         idx += (size_t)gridDim.x * 256) {
        if (idx < PREP_W) {
            size_t m = idx / (576 * WPAD);
            int r = (int)(idx - m * (576 * WPAD));
            int np = r / WPAD, k = r - np * WPAD;
            int j, g;
            col_to_jg(np, j, g);
            w16[idx] = (k < 144)
                ? __float2half(args.wsrc[m][(g * 144 + j) * 144 + k]) : __half(0.f);
        } else if (idx < PREP_W + PREP_B) {
            int e = (int)(idx - PREP_W);
            int b = e / 576, np = e - b * 576;
            int j, g;
            col_to_jg(np, j, g);
            br[e] = args.bih[b][g * 144 + j] + args.bhh[b][g * 144 + j];
        } else if (idx < PREP_W + PREP_B + PREP_F) {
            int e = (int)(idx - PREP_W - PREP_B);
            int n = e / 288, k = e - n * 288;
            fw16[e] = (n < 264) ? __float2half(args.fW[k * 264 + n]) : __half(0.f);
        } else {
            size_t e = idx - PREP_W - PREP_B - PREP_F;
            size_t b = e / 288;
            int r = (int)(e - b * 288);
            int j = r / 24, k = r - j * 24;
            x16[e] = (k < 22) ? __float2half(args.x[b * 264 + j * 22 + k]) : __half(0.f);
        }
    }
}

// Build combined GAT matrix: M^T[n=(i,f)][kk=(j,k)] = P[i,j,h(f)] * W[k,f]
__global__ void build_M(const float* __restrict__ P, const float* __restrict__ W,
                        __half* __restrict__ M, int Nrows, int K,
                        int FPNP, int FV, int KP, int KV) {
    int idx = blockIdx.x * 256 + threadIdx.x;
    if (idx >= Nrows * K) return;
    int n = idx / K, kk = idx - n * K;
    int i = n / FPNP, f = n - i * FPNP;
    int j = kk / KP, k = kk - j * KP;
    float v = 0.f;
    if (f < FV && k < KV && i < 12) {
        int cs = FV >> 2;
        int h = f / cs;
        v = P[(i * 4 + h) * 12 + j] * W[k * FV + f];
    }
    M[idx] = __float2half(v);
}

// ---------------------------------------------------------------------------
// Attention probs for a PAIR of GAT layers (sample 0 only)
// ---------------------------------------------------------------------------
template <int CI1, int CO1, int CI2, int CO2, bool HALFIN>
__global__ void attn_pair(const void* xin,
                          const float* W1, const float* b1, const float* a1,
                          const float* W2, const float* b2, const float* a2,
                          float* probs1, float* probs2) {
    constexpr int CS1 = CO1 / 4, CS2 = CO2 / 4;
    __shared__ float x0[12 * CI1];
    __shared__ float feat[12 * CO1];
    __shared__ float lg[44 * 4];
    __shared__ float h1s[12 * CI2];
    __shared__ float feat2[12 * CO2];
    int tid = threadIdx.x;

    for (int i = tid; i < 12 * CI1; i += 128)
        x0[i] = HALFIN ? __half2float(((const __half*)xin)[i]) : ((const float*)xin)[i];
    __syncthreads();
    for (int idx = tid; idx < 12 * CO1; idx += 128) {
        int i = idx / CO1, f = idx - i * CO1;
        float acc = b1[f];
        for (int k = 0; k < CI1; k++) acc += x0[i * CI1 + k] * W1[k * CO1 + f];
        feat[idx] = acc;
    }
    __syncthreads();
    for (int idx = tid; idx < 176; idx += 128) {
        int e = idx >> 2, h = idx & 3;
        const float* ah = a1 + h * 2 * CS1;
        float s = 0.f;
        for (int c = 0; c < CS1; c++)
            s += ah[c] * feat[c_EI[e] * CO1 + h * CS1 + c] +
                 ah[CS1 + c] * feat[c_EJ[e] * CO1 + h * CS1 + c];
        lg[idx] = s > 0.f ? s : 0.2f * s;
    }
    __syncthreads();
    for (int idx = tid; idx < 48; idx += 128) {
        int i = idx >> 2, h = idx & 3;
        int s0 = c_RS[i], s1 = c_RS[i + 1];
        float m = -3.4e38f;
        for (int e = s0; e < s1; e++) m = fmaxf(m, lg[e * 4 + h]);
        float sum = 0.f;
        for (int e = s0; e < s1; e++) sum += expf(lg[e * 4 + h] - m);
        float* pr = probs1 + (i * 4 + h) * 12;
        for (int j = 0; j < 12; j++) pr[j] = 0.f;
        for (int e = s0; e < s1; e++) pr[c_EJ[e]] = expf(lg[e * 4 + h] - m) / sum;
    }
    __syncthreads();
    for (int idx = tid; idx < 12 * CO1; idx += 128) {
        int i = idx / CO1, f = idx - i * CO1;
        int h = f / CS1;
        const float* pr = probs1 + (i * 4 + h) * 12;
        float acc = 0.f;
        for (int j = 0; j < 12; j++) acc += pr[j] * feat[j * CO1 + f];
        h1s[idx] = acc > 0.f ? acc : expm1f(acc);
    }
    __syncthreads();
    for (int idx = tid; idx < 12 * CO2; idx += 128) {
        int i = idx / CO2, f = idx - i * CO2;
        float acc = b2[f];
        for (int k = 0; k < CI2; k++) acc += h1s[i * CI2 + k] * W2[k * CO2 + f];
        feat2[idx] = acc;
    }
    __syncthreads();
    for (int idx = tid; idx < 176; idx += 128) {
        int e = idx >> 2, h = idx & 3;
        const float* ah = a2 + h * 2 * CS2;
        float s = 0.f;
        for (int c = 0; c < CS2; c++)
            s += ah[c] * feat2[c_EI[e] * CO2 + h * CS2 + c] +
                 ah[CS2 + c] * feat2[c_EJ[e] * CO2 + h * CS2 + c];
        lg[idx] = s > 0.f ? s : 0.2f * s;
    }
    __syncthreads();
    for (int idx = tid; idx < 48; idx += 128) {
        int i = idx >> 2, h = idx & 3;
        int s0 = c_RS[i], s1 = c_RS[i + 1];
        float m = -3.4e38f;
        for (int e = s0; e < s1; e++) m = fmaxf(m, lg[e * 4 + h]);
        float sum = 0.f;
        for (int e = s0; e < s1; e++) sum += expf(lg[e * 4 + h] - m);
        float* pr = probs2 + (i * 4 + h) * 12;
        for (int j = 0; j < 12; j++) pr[j] = 0.f;
        for (int e = s0; e < s1; e++) pr[c_EJ[e]] = expf(lg[e * 4 + h] - m) / sum;
    }
}

// ---------------------------------------------------------------------------
// Unified fp16 GEMM (pre-GEMMs + FC), double-buffered cp.async pipeline.
//  EPI 0: fragment-packed Xpre store; EPI 1: FC + MSE partials
// ---------------------------------------------------------------------------
#define GBUF (256 * 56 + 64 * 56)          // halves per buffer
#define GSMEM (2 * GBUF * 2)               // bytes

template <int EPI>
__global__ __launch_bounds__(128, 2) void gemm2(
    const __half* __restrict__ A, int K,
    const __half* __restrict__ Bw, int ldb,
    __half* __restrict__ C,
    const float* __restrict__ bias,
    const __half* __restrict__ x16, float* __restrict__ part) {
    extern __shared__ __align__(16) __half gsm[];
    const int tid = threadIdx.x;
    const int w = tid >> 5, lane = tid & 31;
    const int grp = lane >> 2, tig = lane & 3;

    float acc[4][8][4];
#pragma unroll
    for (int mt = 0; mt < 4; mt++)
#pragma unroll
        for (int nt = 0; nt < 8; nt++)
#pragma unroll
            for (int i = 0; i < 4; i++) acc[mt][nt][i] = 0.f;

    const size_t mBase = (size_t)blockIdx.y * 256;
    const int nBase = blockIdx.x * 64;

    const int aRow = w * 64 + (lane & 15);
    const int aCol = (lane >> 4) * 8;
    const int bRow = (lane & 7) + ((lane >> 4) & 1) * 8;
    const int bCol = ((lane >> 3) & 1) * 8;

    const int KT = K / 48;

    auto issue = [&](int buf, int k0) {
        __half* As = gsm + buf * GBUF;
        __half* Bs = As + 256 * 56;
#pragma unroll
        for (int i = 0; i < 12; i++) {
            int q = tid + i * 128;
            int row = q / 6, off = (q - row * 6) * 8;
            cp16(As + row * 56 + off, A + (mBase + row) * K + k0 + off);
        }
#pragma unroll
        for (int i = 0; i < 3; i++) {
            int q = tid + i * 128;
            int n = q / 6, off = (q - n * 6) * 8;
            cp16(Bs + n * 56 + off, Bw + (size_t)(nBase + n) * ldb + k0 + off);
        }
        cp_commit();
    };

    issue(0, 0);
    for (int kt = 0; kt < KT; kt++) {
        int cur = kt & 1;
        if (kt + 1 < KT) issue(cur ^ 1, (kt + 1) * 48);
        if (kt + 1 < KT) cp_wait<1>(); else cp_wait<0>();
        __syncthreads();
        __half* As = gsm + cur * GBUF;
        __half* Bs = As + 256 * 56;
#pragma unroll
        for (int kc = 0; kc < 3; kc++) {
            uint32_t a[4][4], b[4][4];
#pragma unroll
            for (int mt = 0; mt < 4; mt++)
                ldm_x4(a[mt][0], a[mt][1], a[mt][2], a[mt][3],
                       As + (aRow + mt * 16) * 56 + kc * 16 + aCol);
#pragma unroll
            for (int g = 0; g < 4; g++)
                ldm_x4(b[g][0], b[g][1], b[g][2], b[g][3],
                       Bs + (bRow + g * 16) * 56 + kc * 16 + bCol);
#pragma unroll
            for (int mt = 0; mt < 4; mt++)
#pragma unroll
                for (int g = 0; g < 4; g++) {
                    MMA16(acc[mt][2*g][0], acc[mt][2*g][1], acc[mt][2*g][2], acc[mt][2*g][3],
                          a[mt][0], a[mt][1], a[mt][2], a[mt][3], b[g][0], b[g][1]);
                    MMA16(acc[mt][2*g+1][0], acc[mt][2*g+1][1], acc[mt][2*g+1][2], acc[mt][2*g+1][3],
                          a[mt][0], a[mt][1], a[mt][2], a[mt][3], b[g][2], b[g][3]);
                }
        }
        __syncthreads();
    }

    if (EPI == 0) {
        const int t = (int)(mBase / BB);
        const size_t rowb = (mBase - (size_t)t * BB) + w * 64;
#pragma unroll
        for (int mt = 0; mt < 4; mt++) {
            const int tile_m = (int)((rowb + mt * 16) >> 4);
#pragma unroll
            for (int nt = 0; nt < 8; nt++) {
                const int tile_n = (nBase + nt * 8) >> 3;
                float* a = acc[mt][nt];
                __half* bp = C + (((size_t)t * 72 + tile_n) * 256 + tile_m) * 128 + 2 * lane;
                *(__half2*)bp = __floats2half2_rn(a[0], a[1]);
                *(__half2*)(bp + 64) = __floats2half2_rn(a[2], a[3]);
            }
        }
    } else {  // FC + MSE partials
        float s[4][2];
#pragma unroll
        for (int mt = 0; mt < 4; mt++) { s[mt][0] = 0.f; s[mt][1] = 0.f; }
#pragma unroll
        for (int mt = 0; mt < 4; mt++)
#pragma unroll
            for (int nt = 0; nt < 8; nt++) {
                int colg = nBase + nt * 8 + 2 * tig;
                if (colg >= 264) continue;
                float* a = acc[mt][nt];
                size_t row0 = mBase + w * 64 + mt * 16 + grp;
                int jn = colg / 22, kn = colg - jn * 22;
                int pc = jn * 24 + kn;
                float bx = bias[colg], by = bias[colg + 1];
                float v0 = a[0] + bx, v1 = a[1] + by, v2 = a[2] + bx, v3 = a[3] + by;
                v0 = v0 >= 0.f ? v0 : 0.01f * v0;
                v1 = v1 >= 0.f ? v1 : 0.01f * v1;
                v2 = v2 >= 0.f ? v2 : 0.01f * v2;
                v3 = v3 >= 0.f ? v3 : 0.01f * v3;
                __half2 xa = *(const __half2*)(x16 + row0 * 288 + pc);
                __half2 xb = *(const __half2*)(x16 + (row0 + 8) * 288 + pc);
                float d0 = __half2float(xa.x) - v0, d1 = __half2float(xa.y) - v1;
                float d2 = __half2float(xb.x) - v2, d3 = __half2float(xb.y) - v3;
                s[mt][0] += d0 * d0 + d1 * d1;
                s[mt][1] += d2 * d2 + d3 * d3;
            }
#pragma unroll
        for (int mt = 0; mt < 4; mt++) {
            size_t row0 = mBase + w * 64 + mt * 16 + grp;
            float v0 = s[mt][0], v1 = s[mt][1];
            v0 += __shfl_xor_sync(0xffffffffu, v0, 1);
            v0 += __shfl_xor_sync(0xffffffffu, v0, 2);
            v1 += __shfl_xor_sync(0xffffffffu, v1, 1);
            v1 += __shfl_xor_sync(0xffffffffu, v1, 2);
            if (tig == 0) {
                part[(size_t)blockIdx.x * NB + row0] = v0;
                part[(size_t)blockIdx.x * NB + row0 + 8] = v1;
            }
        }
    }
}

__global__ void mse_final(const float* __restrict__ part, float* __restrict__ out) {
    int idx = blockIdx.x * 256 + threadIdx.x;
    if (idx >= NB) return;
    float s = 0.f;
#pragma unroll
    for (int k = 0; k < 5; k++) s += part[(size_t)k * NB + idx];
    out[idx] = s * (1.f / 264.f);
}

// ---------------------------------------------------------------------------
// Fused GAT pair: stage1 S = ELU(A @ M1^T + b1) in smem [256][SPAD];
// stage2 C = epilogue(S @ M2^T + b2). 384 blocks x 128 threads.
//  EPI 3: remap col=(i*12+f), f=colg&15<12, ldc 144 (pair A -> h2)
//  EPI 2: guard 288, fpn 24, ldc 288 (pair B -> h4)
// ---------------------------------------------------------------------------
#define SPAD 200
#define S_HALVES (256 * SPAD)

template <int K1, int N2, int EPI>
__global__ __launch_bounds__(128, 1) void gat_fused2(
    const __half* __restrict__ A, const __half* __restrict__ M1,
    const __half* __restrict__ M2, const float* __restrict__ b1f,
    const float* __restrict__ b2f, __half* __restrict__ C) {
    extern __shared__ __align__(16) __half gsm[];
    __half* S    = gsm;                 // [256][SPAD]
    __half* pipe = gsm + S_HALVES;      // stage1: 2 x GBUF   (aliased)
    __half* Bf   = gsm + S_HALVES;      // stage2: [N2][SPAD] (aliased)

    const int tid = threadIdx.x;
    const int w = tid >> 5, lane = tid & 31;
    const int grp = lane >> 2, tig = lane & 3;
    const size_t mBase = (size_t)blockIdx.x * 256;

    const int aRow = w * 64 + (lane & 15);
    const int aCol = (lane >> 4) * 8;
    const int bRow = (lane & 7) + ((lane >> 4) & 1) * 8;
    const int bCol = ((lane >> 3) & 1) * 8;

    // ---- stage 1: 3 n-chunks of 64 -> S ----
    for (int n1 = 0; n1 < 3; n1++) {
        const int nBase = n1 * 64;
        float acc[4][8][4];
#pragma unroll
        for (int mt = 0; mt < 4; mt++)
#pragma unroll
            for (int nt = 0; nt < 8; nt++)
#pragma unroll
                for (int i = 0; i < 4; i++) acc[mt][nt][i] = 0.f;

        const int KT = K1 / 48;
        auto issue = [&](int buf, int k0) {
            __half* As = pipe + buf * GBUF;
            __half* Bs = As + 256 * 56;
#pragma unroll
            for (int i = 0; i < 12; i++) {
                int q = tid + i * 128;
                int row = q / 6, off = (q - row * 6) * 8;
                cp16(As + row * 56 + off, A + (mBase + row) * K1 + k0 + off);
            }
#pragma unroll
            for (int i = 0; i < 3; i++) {
                int q = tid + i * 128;
                int n = q / 6, off = (q - n * 6) * 8;
                cp16(Bs + n * 56 + off, M1 + (size_t)(nBase + n) * K1 + k0 + off);
            }
            cp_commit();
        };
        issue(0, 0);
        for (int kt = 0; kt < KT; kt++) {
            int cur = kt & 1;
            if (kt + 1 < KT) issue(cur ^ 1, (kt + 1) * 48);
            if (kt + 1 < KT) cp_wait<1>(); else cp_wait<0>();
            __syncthreads();
            __half* As = pipe + cur * GBUF;
            __half* Bs = As + 256 * 56;
#pragma unroll
            for (int kc = 0; kc < 3; kc++) {
                uint32_t a[4][4], b[4][4];
#pragma unroll
                for (int mt = 0; mt < 4; mt++)
                    ldm_x4(a[mt][0], a[mt][1], a[mt][2], a[mt][3],
                           As + (aRow + mt * 16) * 56 + kc * 16 + aCol);
#pragma unroll
                for (int g = 0; g < 4; g++)
                    ldm_x4(b[g][0], b[g][1], b[g][2], b[g][3],
                           Bs + (bRow + g * 16) * 56 + kc * 16 + bCol);
#pragma unroll
                for (int mt = 0; mt < 4; mt++)
#pragma unroll
                    for (int g = 0; g < 4; g++) {
                        MMA16(acc[mt][2*g][0], acc[mt][2*g][1], acc[mt][2*g][2], acc[mt][2*g][3],
                              a[mt][0], a[mt][1], a[mt][2], a[mt][3], b[g][0], b[g][1]);
                        MMA16(acc[mt][2*g+1][0], acc[mt][2*g+1][1], acc[mt][2*g+1][2], acc[mt][2*g+1][3],
                              a[mt][0], a[mt][1], a[mt][2], a[mt][3], b[g][2], b[g][3]);
                    }
            }
            __syncthreads();
        }
        // ELU epilogue -> S
#pragma unroll
        for (int mt = 0; mt < 4; mt++)
#pragma unroll
            for (int nt = 0; nt < 8; nt++) {
                int colg = nBase + nt * 8 + 2 * tig;
                int f = colg & 15;
                float bx = b1f[f], by = b1f[f + 1];
                float* a = acc[mt][nt];
                int row0 = w * 64 + mt * 16 + grp;
                *(__half2*)(S + row0 * SPAD + colg) =
                    __floats2half2_rn(felu(a[0] + bx), felu(a[1] + by));
                *(__half2*)(S + (row0 + 8) * SPAD + colg) =
                    __floats2half2_rn(felu(a[2] + bx), felu(a[3] + by));
            }
        __syncthreads();
    }

    // ---- load full M2 into Bf ----
    for (int i = tid; i < N2 * 24; i += 128) {
        int n = i / 24, ch = i - n * 24;
        cp16(Bf + n * SPAD + ch * 8, M2 + (size_t)n * 192 + ch * 8);
    }
    cp_commit();
    cp_wait<0>();
    __syncthreads();

    // ---- stage 2: N2/64 chunks ----
    for (int n2 = 0; n2 < N2 / 64; n2++) {
        float acc[4][8][4];
#pragma unroll
        for (int mt = 0; mt < 4; mt++)
#pragma unroll
            for (int nt = 0; nt < 8; nt++)
#pragma unroll
                for (int i = 0; i < 4; i++) acc[mt][nt][i] = 0.f;
#pragma unroll
        for (int kc = 0; kc < 12; kc++) {
            uint32_t a[4][4], b[4][4];
#pragma unroll
            for (int mt = 0; mt < 4; mt++)
                ldm_x4(a[mt][0], a[mt][1], a[mt][2], a[mt][3],
                       S + (aRow + mt * 16) * SPAD + kc * 16 + aCol);
#pragma unroll
            for (int g = 0; g < 4; g++)
                ldm_x4(b[g][0], b[g][1], b[g][2], b[g][3],
                       Bf + (n2 * 64 + bRow + g * 16) * SPAD + kc * 16 + bCol);
#pragma unroll
            for (int mt = 0; mt < 4; mt++)
#pragma unroll
                for (int g = 0; g < 4; g++) {
                    MMA16(acc[mt][2*g][0], acc[mt][2*g][1], acc[mt][2*g][2], acc[mt][2*g][3],
                          a[mt][0], a[mt][1], a[mt][2], a[mt][3], b[g][0], b[g][1]);
                    MMA16(acc[mt][2*g+1][0], acc[mt][2*g+1][1], acc[mt][2*g+1][2], acc[mt][2*g+1][3],
                          a[mt][0], a[mt][1], a[mt][2], a[mt][3], b[g][2], b[g][3]);
                }
        }
#pragma unroll
        for (int mt = 0; mt < 4; mt++)
#pragma unroll
            for (int nt = 0; nt < 8; nt++) {
                int colg = n2 * 64 + nt * 8 + 2 * tig;
                float* a = acc[mt][nt];
                size_t row0 = mBase + w * 64 + mt * 16 + grp;
                if (EPI == 3) {
                    int f = colg & 15;
                    if (f >= 12) continue;
                    int i = colg >> 4;
                    int oc = i * 12 + f;
                    float bx = b2f[f], by = b2f[f + 1];
                    *(__half2*)(C + row0 * 144 + oc) =
                        __floats2half2_rn(felu(a[0] + bx), felu(a[1] + by));
                    *(__half2*)(C + (row0 + 8) * 144 + oc) =
                        __floats2half2_rn(felu(a[2] + bx), felu(a[3] + by));
                } else {
                    if (colg >= 288) continue;
                    int f = colg % 24;
                    float bx = b2f[f], by = b2f[f + 1];
                    *(__half2*)(C + row0 * 288 + colg) =
                        __floats2half2_rn(felu(a[0] + bx), felu(a[1] + by));
                    *(__half2*)(C + (row0 + 8) * 288 + colg) =
                        __floats2half2_rn(felu(a[2] + bx), felu(a[3] + by));
                }
            }
    }
}

// ---------------------------------------------------------------------------
// Persistent LSTM chain (unchanged from round 14)
// ---------------------------------------------------------------------------
#define CHAIN_SMEM (576 * WPAD * 2 + 2 * 32 * WPAD * 2 + 576 * 4)

__global__ __launch_bounds__(256, 1) void lstm_chain(
    const __half* __restrict__ W16, const float* __restrict__ bias,
    const __half* __restrict__ xpre, const __half* __restrict__ hInit,
    __half* __restrict__ y, size_t yStride) {
    extern __shared__ __align__(16) unsigned char smem_raw[];
    __half* Ws  = (__half*)smem_raw;
    __half* h0s = Ws + 576 * WPAD;
    __half* h1s = h0s + 32 * WPAD;
    float*  bs  = (float*)(h1s + 32 * WPAD);

    const int tid = threadIdx.x;
    const int w = tid >> 5, lane = tid & 31;
    const int warpM = w >> 2, warpN = w & 3;
    const int grp = lane >> 2, tig = lane & 3;
    const size_t gRowBase = (size_t)blockIdx.x * 32;

    {
        const uint4* src = (const uint4*)W16;
        uint4* dst = (uint4*)Ws;
        for (int i = tid; i < 576 * WPAD / 8; i += 256) dst[i] = src[i];
    }
    for (int i = tid; i < 32 * WPAD; i += 256) { h0s[i] = __half(0.f); h1s[i] = __half(0.f); }
    for (int i = tid; i < 576; i += 256) bs[i] = bias[i];
    __syncthreads();
    if (hInit) {
        for (int i = tid; i < 32 * 144; i += 256) {
            int r = i / 144, j = i - r * 144;
            h0s[r * WPAD + j] = hInit[(gRowBase + r) * 144 + j];
        }
        __syncthreads();
    }

    const int aRow = warpM * 16 + (lane & 15);
    const int aCol = (lane >> 4) * 8;
    const int bRowBase = warpN * 144 + (lane & 7) + ((lane >> 4) & 1) * 8;
    const int bCol = ((lane >> 3) & 1) * 8;
    const int tile_m = blockIdx.x * 2 + warpM;
    const int rbase = warpM * 16 + grp;

    float creg[9][2];
#pragma unroll
    for (int s = 0; s < 9; s++) { creg[s][0] = 0.f; creg[s][1] = 0.f; }

    int p = 0;
    for (int t = 0; t < PERIOD; t++) {
        const __half* hc = p ? h1s : h0s;
        __half* hn = p ? h0s : h1s;
        const __half* xslice = xpre ? (xpre + (size_t)t * BB * 576) : nullptr;

        uint32_t Areg[9][4];
#pragma unroll
        for (int kc = 0; kc < 9; kc++)
            ldm_x4(Areg[kc][0], Areg[kc][1], Areg[kc][2], Areg[kc][3],
                   hc + aRow * WPAD + kc * 16 + aCol);

        float gif[9][4];
#pragma unroll
        for (int np = 0; np < 9; np++) {
            float d[2][4];
#pragma unroll
            for (int u = 0; u < 2; u++)
#pragma unroll
                for (int i = 0; i < 4; i++) d[u][i] = 0.f;
            const __half* wb = Ws + (bRowBase + np * 16) * WPAD + bCol;
#pragma unroll
            for (int kc = 0; kc < 9; kc++) {
                uint32_t b0, b1, b2, b3;
                ldm_x4(b0, b1, b2, b3, wb + kc * 16);
                MMA16(d[0][0], d[0][1], d[0][2], d[0][3],
                      Areg[kc][0], Areg[kc][1], Areg[kc][2], Areg[kc][3], b0, b1);
                MMA16(d[1][0], d[1][1], d[1][2], d[1][3],
                      Areg[kc][0], Areg[kc][1], Areg[kc][2], Areg[kc][3], b2, b3);
            }
#pragma unroll
            for (int u = 0; u < 2; u++) {
                int q = 2 * np + u;
                int colg = warpN * 144 + q * 8 + 2 * tig;
                float v0 = d[u][0] + bs[colg], v1 = d[u][1] + bs[colg + 1];
                float v2 = d[u][2] + bs[colg], v3 = d[u][3] + bs[colg + 1];
                if (xslice) {
                    int tile_n = warpN * 18 + q;
                    const __half* tb = xslice +
                        (((size_t)tile_n) * 256 + tile_m) * 128 + 2 * lane;
                    __half2 x01 = *(const __half2*)tb;
                    __half2 x23 = *(const __half2*)(tb + 64);
                    v0 += __half2float(x01.x); v1 += __half2float(x01.y);
                    v2 += __half2float(x23.x); v3 += __half2float(x23.y);
                }
                if (q < 9) {
                    gif[q][0] = v0; gif[q][1] = v1; gif[q][2] = v2; gif[q][3] = v3;
                } else {
                    int s = q - 9;
                    int j = warpN * 36 + s * 4 + tig;
                    float c2a = sigm(gif[s][1]) * creg[s][0] + sigm(gif[s][0]) * tanha(v0);
                    float h2a = sigm(v1) * tanha(c2a);
                    creg[s][0] = c2a;
                    hn[rbase * WPAD + j] = __float2half(h2a);
                    float c2b = sigm(gif[s][3]) * creg[s][1] + sigm(gif[s][2]) * tanha(v2);
                    float h2b = sigm(v3) * tanha(c2b);
                    creg[s][1] = c2b;
                    hn[(rbase + 8) * WPAD + j] = __float2half(h2b);
                }
            }
        }
        __syncthreads();
        if (yStride != 0 || t == PERIOD - 1) {
            __half* yslice = y + (size_t)t * yStride;
            for (int i = tid; i < 32 * 18; i += 256) {
                int r = i / 18, q = i - r * 18;
                *(uint4*)(yslice + (gRowBase + r) * 144 + q * 8) =
                    *(const uint4*)(hn + r * WPAD + q * 8);
            }
        }
        p ^= 1;
    }
}

// ---------------------------------------------------------------------------
// Host orchestration
// ---------------------------------------------------------------------------
extern "C" void kernel_launch(void* const* d_in, const int* in_sizes, int n_in,
                              void* d_out, int out_size) {
    const float* x     = (const float*)d_in[0];
    const float* gW0   = (const float*)d_in[1];
    const float* gb0   = (const float*)d_in[2];
    const float* ga0   = (const float*)d_in[3];
    const float* gW1   = (const float*)d_in[4];
    const float* gb1   = (const float*)d_in[5];
    const float* ga1   = (const float*)d_in[6];
    const float* eWih0 = (const float*)d_in[7];
    const float* eWhh0 = (const float*)d_in[8];
    const float* ebih0 = (const float*)d_in[9];
    const float* ebhh0 = (const float*)d_in[10];
    const float* eWih1 = (const float*)d_in[11];
    const float* eWhh1 = (const float*)d_in[12];
    const float* ebih1 = (const float*)d_in[13];
    const float* ebhh1 = (const float*)d_in[14];
    const float* dWhh0 = (const float*)d_in[16];
    const float* dbih0 = (const float*)d_in[17];
    const float* dbhh0 = (const float*)d_in[18];
    const float* dWih1 = (const float*)d_in[19];
    const float* dWhh1 = (const float*)d_in[20];
    const float* dbih1 = (const float*)d_in[21];
    const float* dbhh1 = (const float*)d_in[22];
    const float* gW3   = (const float*)d_in[23];
    const float* gb3   = (const float*)d_in[24];
    const float* ga3   = (const float*)d_in[25];
    const float* gW4   = (const float*)d_in[26];
    const float* gb4   = (const float*)d_in[27];
    const float* ga4   = (const float*)d_in[28];
    const float* fW    = (const float*)d_in[29];
    const float* fb    = (const float*)d_in[30];

    float* S = nullptr;
    cudaGetSymbolAddress((void**)&S, g_scratch);

    __half* x16     = (__half*)(S + OFF_X16);
    __half* h2_16   = (__half*)(S + OFF_H2);
    __half* Xpre16  = (__half*)(S + OFF_XPRE);
    __half* y0_16   = (__half*)(S + OFF_Y0);
    __half* yd0_16  = (__half*)(S + OFF_YD0);
    __half* yd1_16  = (__half*)(S + OFF_YD1);
    __half* h4_16   = (__half*)(S + OFF_H4);
    __half* enc1_16 = (__half*)(S + OFF_ENC1);
    float*  part    = S + OFF_PART;
    float*  probs   = S + OFF_PROBS;
    __half* Mb      = (__half*)(S + OFF_M);
    __half* w16     = (__half*)(S + OFF_W16);
    float*  br      = S + OFF_BR;
    __half* fw16    = (__half*)(S + OFF_FW16);

    __half* M1 = Mb;
    __half* M2 = M1 + 192 * 288;
    __half* M3 = M2 + 192 * 192;
    __half* M4 = M3 + 192 * 144;

    const size_t WSLICE = (size_t)576 * WPAD;
    __half* w_eWih0 = w16 + 0 * WSLICE;
    __half* w_eWhh0 = w16 + 1 * WSLICE;
    __half* w_eWih1 = w16 + 2 * WSLICE;
    __half* w_eWhh1 = w16 + 3 * WSLICE;
    __half* w_dWhh0 = w16 + 4 * WSLICE;
    __half* w_dWih1 = w16 + 5 * WSLICE;
    __half* w_dWhh1 = w16 + 6 * WSLICE;

    const int GATA_SMEM = (S_HALVES + 192 * SPAD) * 2;   // 179200
    const int GATB_SMEM = (S_HALVES + 320 * SPAD) * 2;   // 230400

    cudaFuncSetAttribute(lstm_chain, cudaFuncAttributeMaxDynamicSharedMemorySize,
                         CHAIN_SMEM);
    cudaFuncSetAttribute(gemm2<0>, cudaFuncAttributeMaxDynamicSharedMemorySize, GSMEM);
    cudaFuncSetAttribute(gemm2<1>, cudaFuncAttributeMaxDynamicSharedMemorySize, GSMEM);
    cudaFuncSetAttribute(gat_fused2<288, 192, 3>,
                         cudaFuncAttributeMaxDynamicSharedMemorySize, GATA_SMEM);
    cudaFuncSetAttribute(gat_fused2<144, 320, 2>,
                         cudaFuncAttributeMaxDynamicSharedMemorySize, GATB_SMEM);

    PrepArgs pa;
    pa.wsrc[0] = eWih0; pa.wsrc[1] = eWhh0; pa.wsrc[2] = eWih1; pa.wsrc[3] = eWhh1;
    pa.wsrc[4] = dWhh0; pa.wsrc[5] = dWih1; pa.wsrc[6] = dWhh1;
    pa.bih[0] = ebih0; pa.bih[1] = ebih1; pa.bih[2] = dbih0; pa.bih[3] = dbih1;
    pa.bhh[0] = ebhh0; pa.bhh[1] = ebhh1; pa.bhh[2] = dbhh0; pa.bhh[3] = dbhh1;
    pa.fW = fW;
    pa.x = x;
    prep_all<<<4096, 256>>>(pa, w16, br, fw16, x16);

    // ---- GAT 1+2 fused ----
    attn_pair<22, 16, 16, 12, false><<<1, 128>>>(x, gW0, gb0, ga0, gW1, gb1, ga1,
                                                 probs, probs + 576);
    build_M<<<(192 * 288 + 255) / 256, 256>>>(probs, gW0, M1, 192, 288, 16, 16, 24, 22);
    build_M<<<(192 * 192 + 255) / 256, 256>>>(probs + 576, gW1, M2, 192, 192, 16, 12, 16, 16);
    gat_fused2<288, 192, 3><<<NB / 256, 128, GATA_SMEM>>>(x16, M1, M2, gb0, gb1, h2_16);

    // ---- Encoder layer 0 ----
    gemm2<0><<<dim3(9, NB / 256), 128, GSMEM>>>(h2_16, 144, w_eWih0, WPAD, Xpre16,
                                                nullptr, nullptr, nullptr);
    lstm_chain<<<BB / 32, 256, CHAIN_SMEM>>>(w_eWhh0, br + 0, Xpre16, nullptr,
                                             y0_16, (size_t)BB * 144);
    // ---- Encoder layer 1 (final h only) ----
    gemm2<0><<<dim3(9, NB / 256), 128, GSMEM>>>(y0_16, 144, w_eWih1, WPAD, Xpre16,
                                                nullptr, nullptr, nullptr);
    lstm_chain<<<BB / 32, 256, CHAIN_SMEM>>>(w_eWhh1, br + 576, Xpre16, nullptr,
                                             enc1_16, 0);
    // ---- Decoder layer 0 (zero inputs; h0 = enc0 final = y0[t=23]) ----
    lstm_chain<<<BB / 32, 256, CHAIN_SMEM>>>(w_dWhh0, br + 1152, nullptr,
                                             y0_16 + (size_t)23 * BB * 144,
                                             yd0_16, (size_t)BB * 144);
    // ---- Decoder layer 1 (h0 = enc1 final) ----
    gemm2<0><<<dim3(9, NB / 256), 128, GSMEM>>>(yd0_16, 144, w_dWih1, WPAD, Xpre16,
                                                nullptr, nullptr, nullptr);
    lstm_chain<<<BB / 32, 256, CHAIN_SMEM>>>(w_dWhh1, br + 1728, Xpre16, enc1_16,
                                             yd1_16, (size_t)BB * 144);

    // ---- GAT 3+4 fused ----
    attn_pair<12, 16, 16, 24, true><<<1, 128>>>(yd1_16, gW3, gb3, ga3, gW4, gb4, ga4,
                                                probs + 1152, probs + 1728);
    build_M<<<(192 * 144 + 255) / 256, 256>>>(probs + 1152, gW3, M3, 192, 144, 16, 16, 12, 12);
    build_M<<<(320 * 192 + 255) / 256, 256>>>(probs + 1728, gW4, M4, 320, 192, 24, 24, 16, 16);
    gat_fused2<144, 320, 2><<<NB / 256, 128, GATB_SMEM>>>(yd1_16, M3, M4, gb3, gb4, h4_16);

    // ---- FC + leaky + MSE ----
    gemm2<1><<<dim3(5, NB / 256), 128, GSMEM>>>(h4_16, 288, fw16, 288, nullptr,
                                                fb, x16, part);
    mse_final<<<(NB + 255) / 256, 256>>>(part, (float*)d_out);
}